// round 1
// baseline (speedup 1.0000x reference)
#include <cuda_runtime.h>
#include <cstdint>

#define DEVINL __device__ __forceinline__

namespace cfg {
constexpr int B = 2, S = 2048, D = 1024, H = 16, DH = 64;
constexpr int MR = B * S;  // 4096 rows for projection GEMMs
}

// ---------------- scratch (device globals; no allocation allowed) ----------
__device__ float g_q[(size_t)cfg::B * cfg::S * cfg::D];
__device__ float g_k[(size_t)cfg::B * cfg::S * cfg::D];
__device__ float g_v[(size_t)cfg::B * cfg::S * cfg::D];
__device__ float g_ctx[(size_t)cfg::B * cfg::S * cfg::D];
__device__ float g_m[cfg::B * cfg::H * cfg::S];
__device__ float g_l[cfg::B * cfg::H * cfg::S];
__device__ int   g_maskmode;   // 0=int32, 1=uint8, 2=float32

// ---------------- helpers ---------------------------------------------------
DEVINL unsigned f2tf(float x) {
  unsigned r;
  asm("cvt.rna.tf32.f32 %0, %1;" : "=r"(r) : "f"(x));
  return r;
}
DEVINL float f2tf_f(float x) { return __uint_as_float(f2tf(x)); }

DEVINL void mma_tf32(float c[4], unsigned a0, unsigned a1, unsigned a2, unsigned a3,
                     unsigned b0, unsigned b1) {
  asm volatile(
      "mma.sync.aligned.m16n8k8.row.col.f32.tf32.tf32.f32 "
      "{%0,%1,%2,%3}, {%4,%5,%6,%7}, {%8,%9}, {%0,%1,%2,%3};"
      : "+f"(c[0]), "+f"(c[1]), "+f"(c[2]), "+f"(c[3])
      : "r"(a0), "r"(a1), "r"(a2), "r"(a3), "r"(b0), "r"(b1));
}

DEVINL int mask_on(const void* mask, int mode, int idx) {
  if (mode == 1) return ((const uint8_t*)mask)[idx] != 0;
  if (mode == 2) return ((const float*)mask)[idx] != 0.0f;
  return ((const int*)mask)[idx] != 0;
}

// ---------------- mask dtype detection -------------------------------------
// mask has B*S = 4096 elements -> at least 4096 bytes under any encoding.
// int32 0/1 -> all words <= 1. uint8 packed -> words with value > 1 appear
// (e.g. 0x00010001), never 0x3F800000. float 0.0/1.0 -> words == 0x3F800000.
__global__ void detect_mask_kernel(const unsigned* m) {
  int lane = threadIdx.x;
  int isf = 0, big = 0;
  for (int i = lane; i < 1024; i += 32) {
    unsigned v = m[i];
    if (v == 0x3F800000u) isf = 1;
    else if (v > 1u) big = 1;
  }
  isf = __any_sync(0xFFFFFFFFu, isf);
  big = __any_sync(0xFFFFFFFFu, big);
  if (lane == 0) g_maskmode = isf ? 2 : (big ? 1 : 0);
}

// ---------------- projection GEMM: Y[M,N] = X[M,K] @ W[K,N] + bias ---------
// 3xTF32 split (hi/lo) for near-fp32 accuracy. M=4096, N=K=1024.
// Tiles: BM=128, BN=64, BK=16; 256 threads = 8 warps (4x2), warp tile 32x32.
__global__ void __launch_bounds__(256) proj_kernel(
    const float* __restrict__ X, const float* __restrict__ W,
    const float* __restrict__ bias, float* __restrict__ Y) {
  constexpr int PBM = 128, PBK = 16;
  constexpr int ASTR = 20;   // conflict-free for a-frag pattern (4r+c distinct)
  constexpr int BSTR = 72;   // conflict-free for b-frag pattern (8r+c distinct)
  __shared__ float sAh[PBM * ASTR], sAl[PBM * ASTR];
  __shared__ float sBh[PBK * BSTR], sBl[PBK * BSTR];

  const int N = cfg::D, K = cfg::D;
  const int m0 = blockIdx.y * PBM, n0 = blockIdx.x * 64;
  const int tid = threadIdx.x, lane = tid & 31, warp = tid >> 5;
  const int wm0 = (warp >> 1) * 32, wn0 = (warp & 1) * 32;

  float acc[2][4][4];
#pragma unroll
  for (int i = 0; i < 2; i++)
#pragma unroll
    for (int j = 0; j < 4; j++)
#pragma unroll
      for (int k = 0; k < 4; k++) acc[i][j][k] = 0.0f;

  for (int k0 = 0; k0 < K; k0 += PBK) {
    // A tile 128x16 : 512 float4, 2 per thread
#pragma unroll
    for (int t = 0; t < 2; t++) {
      int idx = tid + t * 256;
      int r = idx >> 2, c = (idx & 3) * 4;
      float4 v = *(const float4*)&X[(size_t)(m0 + r) * K + k0 + c];
      float h;
      h = f2tf_f(v.x); sAh[r * ASTR + c + 0] = h; sAl[r * ASTR + c + 0] = f2tf_f(v.x - h);
      h = f2tf_f(v.y); sAh[r * ASTR + c + 1] = h; sAl[r * ASTR + c + 1] = f2tf_f(v.y - h);
      h = f2tf_f(v.z); sAh[r * ASTR + c + 2] = h; sAl[r * ASTR + c + 2] = f2tf_f(v.z - h);
      h = f2tf_f(v.w); sAh[r * ASTR + c + 3] = h; sAl[r * ASTR + c + 3] = f2tf_f(v.w - h);
    }
    // B tile 16x64 : 256 float4, 1 per thread
    {
      int r = tid >> 4, c = (tid & 15) * 4;
      float4 v = *(const float4*)&W[(size_t)(k0 + r) * N + n0 + c];
      float h;
      h = f2tf_f(v.x); sBh[r * BSTR + c + 0] = h; sBl[r * BSTR + c + 0] = f2tf_f(v.x - h);
      h = f2tf_f(v.y); sBh[r * BSTR + c + 1] = h; sBl[r * BSTR + c + 1] = f2tf_f(v.y - h);
      h = f2tf_f(v.z); sBh[r * BSTR + c + 2] = h; sBl[r * BSTR + c + 2] = f2tf_f(v.z - h);
      h = f2tf_f(v.w); sBh[r * BSTR + c + 3] = h; sBl[r * BSTR + c + 3] = f2tf_f(v.w - h);
    }
    __syncthreads();
#pragma unroll
    for (int ks = 0; ks < 2; ks++) {
      unsigned ah[2][4], al[2][4];
      const int ac = ks * 8 + (lane & 3);
#pragma unroll
      for (int mi = 0; mi < 2; mi++) {
        int r = wm0 + mi * 16 + (lane >> 2);
        ah[mi][0] = __float_as_uint(sAh[r * ASTR + ac]);
        ah[mi][1] = __float_as_uint(sAh[(r + 8) * ASTR + ac]);
        ah[mi][2] = __float_as_uint(sAh[r * ASTR + ac + 4]);
        ah[mi][3] = __float_as_uint(sAh[(r + 8) * ASTR + ac + 4]);
        al[mi][0] = __float_as_uint(sAl[r * ASTR + ac]);
        al[mi][1] = __float_as_uint(sAl[(r + 8) * ASTR + ac]);
        al[mi][2] = __float_as_uint(sAl[r * ASTR + ac + 4]);
        al[mi][3] = __float_as_uint(sAl[(r + 8) * ASTR + ac + 4]);
      }
#pragma unroll
      for (int ni = 0; ni < 4; ni++) {
        int bc = wn0 + ni * 8 + (lane >> 2);
        int br = ks * 8 + (lane & 3);
        unsigned bh0 = __float_as_uint(sBh[br * BSTR + bc]);
        unsigned bh1 = __float_as_uint(sBh[(br + 4) * BSTR + bc]);
        unsigned bl0 = __float_as_uint(sBl[br * BSTR + bc]);
        unsigned bl1 = __float_as_uint(sBl[(br + 4) * BSTR + bc]);
#pragma unroll
        for (int mi = 0; mi < 2; mi++) {
          mma_tf32(acc[mi][ni], ah[mi][0], ah[mi][1], ah[mi][2], ah[mi][3], bh0, bh1);
          mma_tf32(acc[mi][ni], ah[mi][0], ah[mi][1], ah[mi][2], ah[mi][3], bl0, bl1);
          mma_tf32(acc[mi][ni], al[mi][0], al[mi][1], al[mi][2], al[mi][3], bh0, bh1);
        }
      }
    }
    __syncthreads();
  }
#pragma unroll
  for (int mi = 0; mi < 2; mi++) {
#pragma unroll
    for (int ni = 0; ni < 4; ni++) {
      int r = m0 + wm0 + mi * 16 + (lane >> 2);
      int c = n0 + wn0 + ni * 8 + 2 * (lane & 3);
      float2 bb = *(const float2*)&bias[c];
      *(float2*)&Y[(size_t)r * N + c] =
          make_float2(acc[mi][ni][0] + bb.x, acc[mi][ni][1] + bb.y);
      *(float2*)&Y[(size_t)(r + 8) * N + c] =
          make_float2(acc[mi][ni][2] + bb.x, acc[mi][ni][3] + bb.y);
    }
  }
}

// ---------------- attention pass 1: per-row softmax stats (m, l) -----------
// grid (S/64, H, B), 128 threads (4 warps, warp w owns q-rows w*16..w*16+15)
__global__ void __launch_bounds__(128) attn_pass1(const void* __restrict__ mask) {
  using namespace cfg;
  extern __shared__ float smem[];
  float* sQ = smem;                 // 64 x 68
  float* sK = sQ + 64 * 68;         // 64 x 68
  float* sMadd = sK + 64 * 68;      // 64
  const int q0 = blockIdx.x * 64, h = blockIdx.y, b = blockIdx.z;
  const int tid = threadIdx.x, lane = tid & 31, w = tid >> 5;
  const int mode = g_maskmode;

  for (int i = tid; i < 1024; i += 128) {
    int r = i >> 4, c = (i & 15) * 4;
    float4 v = *(const float4*)&g_q[((size_t)(b * S) + q0 + r) * D + h * DH + c];
    *(float4*)&sQ[r * 68 + c] =
        make_float4(f2tf_f(v.x * 0.125f), f2tf_f(v.y * 0.125f),
                    f2tf_f(v.z * 0.125f), f2tf_f(v.w * 0.125f));
  }

  float m_run[2] = {-1e30f, -1e30f}, l_run[2] = {0.0f, 0.0f};

  for (int kt = 0; kt < S / 64; kt++) {
    __syncthreads();
    const int k0 = kt * 64;
    for (int i = tid; i < 1024; i += 128) {
      int r = i >> 4, c = (i & 15) * 4;
      float4 v = *(const float4*)&g_k[((size_t)(b * S) + k0 + r) * D + h * DH + c];
      *(float4*)&sK[r * 68 + c] =
          make_float4(f2tf_f(v.x), f2tf_f(v.y), f2tf_f(v.z), f2tf_f(v.w));
    }
    if (tid < 64) sMadd[tid] = mask_on(mask, mode, b * S + k0 + tid) ? 0.0f : -1e30f;
    __syncthreads();

    float sc[8][4];
#pragma unroll
    for (int ni = 0; ni < 8; ni++) { sc[ni][0] = sc[ni][1] = sc[ni][2] = sc[ni][3] = 0.0f; }
#pragma unroll
    for (int ks = 0; ks < 8; ks++) {
      int ar = w * 16 + (lane >> 2), ac = ks * 8 + (lane & 3);
      unsigned a0 = __float_as_uint(sQ[ar * 68 + ac]);
      unsigned a1 = __float_as_uint(sQ[(ar + 8) * 68 + ac]);
      unsigned a2 = __float_as_uint(sQ[ar * 68 + ac + 4]);
      unsigned a3 = __float_as_uint(sQ[(ar + 8) * 68 + ac + 4]);
#pragma unroll
      for (int ni = 0; ni < 8; ni++) {
        int bn = ni * 8 + (lane >> 2), bd = ks * 8 + (lane & 3);
        unsigned b0 = __float_as_uint(sK[bn * 68 + bd]);
        unsigned b1 = __float_as_uint(sK[bn * 68 + bd + 4]);
        mma_tf32(sc[ni], a0, a1, a2, a3, b0, b1);
      }
    }
    float tmax0 = -1e30f, tmax1 = -1e30f;
#pragma unroll
    for (int ni = 0; ni < 8; ni++) {
      int c = ni * 8 + 2 * (lane & 3);
      float a0 = sMadd[c], a1 = sMadd[c + 1];
      sc[ni][0] += a0; sc[ni][1] += a1; sc[ni][2] += a0; sc[ni][3] += a1;
      tmax0 = fmaxf(tmax0, fmaxf(sc[ni][0], sc[ni][1]));
      tmax1 = fmaxf(tmax1, fmaxf(sc[ni][2], sc[ni][3]));
    }
    tmax0 = fmaxf(tmax0, __shfl_xor_sync(0xFFFFFFFFu, tmax0, 1));
    tmax0 = fmaxf(tmax0, __shfl_xor_sync(0xFFFFFFFFu, tmax0, 2));
    tmax1 = fmaxf(tmax1, __shfl_xor_sync(0xFFFFFFFFu, tmax1, 1));
    tmax1 = fmaxf(tmax1, __shfl_xor_sync(0xFFFFFFFFu, tmax1, 2));
    float mn0 = fmaxf(m_run[0], tmax0), mn1 = fmaxf(m_run[1], tmax1);
    float ts0 = 0.0f, ts1 = 0.0f;
#pragma unroll
    for (int ni = 0; ni < 8; ni++) {
      ts0 += __expf(sc[ni][0] - mn0) + __expf(sc[ni][1] - mn0);
      ts1 += __expf(sc[ni][2] - mn1) + __expf(sc[ni][3] - mn1);
    }
    ts0 += __shfl_xor_sync(0xFFFFFFFFu, ts0, 1);
    ts0 += __shfl_xor_sync(0xFFFFFFFFu, ts0, 2);
    ts1 += __shfl_xor_sync(0xFFFFFFFFu, ts1, 1);
    ts1 += __shfl_xor_sync(0xFFFFFFFFu, ts1, 2);
    l_run[0] = l_run[0] * __expf(m_run[0] - mn0) + ts0; m_run[0] = mn0;
    l_run[1] = l_run[1] * __expf(m_run[1] - mn1) + ts1; m_run[1] = mn1;
  }
  if ((lane & 3) == 0) {
    size_t base = (size_t)(b * H + h) * S;
    int r = q0 + w * 16 + (lane >> 2);
    g_m[base + r] = m_run[0];     g_l[base + r] = l_run[0];
    g_m[base + r + 8] = m_run[1]; g_l[base + r + 8] = l_run[1];
  }
}

// ---------------- attention pass 2: attn write + ctx = P @ V ---------------
__global__ void __launch_bounds__(128) attn_pass2(const void* __restrict__ mask,
                                                  float* __restrict__ attn) {
  using namespace cfg;
  extern __shared__ float smem[];
  float* sQ = smem;                  // 64 x 68
  float* sK = sQ + 64 * 68;          // 64 x 68
  float* sV = sK + 64 * 68;          // 64 x 72
  float* sP = sV + 64 * 72;          // 64 x 68
  float* sMadd = sP + 64 * 68;       // 64
  const int q0 = blockIdx.x * 64, h = blockIdx.y, b = blockIdx.z;
  const int tid = threadIdx.x, lane = tid & 31, w = tid >> 5;
  const int mode = g_maskmode;

  for (int i = tid; i < 1024; i += 128) {
    int r = i >> 4, c = (i & 15) * 4;
    float4 v = *(const float4*)&g_q[((size_t)(b * S) + q0 + r) * D + h * DH + c];
    *(float4*)&sQ[r * 68 + c] =
        make_float4(f2tf_f(v.x * 0.125f), f2tf_f(v.y * 0.125f),
                    f2tf_f(v.z * 0.125f), f2tf_f(v.w * 0.125f));
  }

  size_t mbase = (size_t)(b * H + h) * S;
  int myrow = q0 + w * 16 + (lane >> 2);
  float mr0 = g_m[mbase + myrow], mr1 = g_m[mbase + myrow + 8];
  float il0 = 1.0f / g_l[mbase + myrow], il1 = 1.0f / g_l[mbase + myrow + 8];

  float ctx[8][4];
#pragma unroll
  for (int ni = 0; ni < 8; ni++) { ctx[ni][0] = ctx[ni][1] = ctx[ni][2] = ctx[ni][3] = 0.0f; }

  for (int kt = 0; kt < S / 64; kt++) {
    __syncthreads();
    const int k0 = kt * 64;
    for (int i = tid; i < 1024; i += 128) {
      int r = i >> 4, c = (i & 15) * 4;
      float4 vk = *(const float4*)&g_k[((size_t)(b * S) + k0 + r) * D + h * DH + c];
      *(float4*)&sK[r * 68 + c] =
          make_float4(f2tf_f(vk.x), f2tf_f(vk.y), f2tf_f(vk.z), f2tf_f(vk.w));
      float4 vv = *(const float4*)&g_v[((size_t)(b * S) + k0 + r) * D + h * DH + c];
      *(float4*)&sV[r * 72 + c] =
          make_float4(f2tf_f(vv.x), f2tf_f(vv.y), f2tf_f(vv.z), f2tf_f(vv.w));
    }
    if (tid < 64) sMadd[tid] = mask_on(mask, mode, b * S + k0 + tid) ? 0.0f : -1e30f;
    __syncthreads();

    float sc[8][4];
#pragma unroll
    for (int ni = 0; ni < 8; ni++) { sc[ni][0] = sc[ni][1] = sc[ni][2] = sc[ni][3] = 0.0f; }
#pragma unroll
    for (int ks = 0; ks < 8; ks++) {
      int ar = w * 16 + (lane >> 2), ac = ks * 8 + (lane & 3);
      unsigned a0 = __float_as_uint(sQ[ar * 68 + ac]);
      unsigned a1 = __float_as_uint(sQ[(ar + 8) * 68 + ac]);
      unsigned a2 = __float_as_uint(sQ[ar * 68 + ac + 4]);
      unsigned a3 = __float_as_uint(sQ[(ar + 8) * 68 + ac + 4]);
#pragma unroll
      for (int ni = 0; ni < 8; ni++) {
        int bn = ni * 8 + (lane >> 2), bd = ks * 8 + (lane & 3);
        unsigned b0 = __float_as_uint(sK[bn * 68 + bd]);
        unsigned b1 = __float_as_uint(sK[bn * 68 + bd + 4]);
        mma_tf32(sc[ni], a0, a1, a2, a3, b0, b1);
      }
    }
    // p = exp(s + maskadd - m) / l; stage into sP (warp-private rows)
    const int rl = w * 16 + (lane >> 2);
#pragma unroll
    for (int ni = 0; ni < 8; ni++) {
      int c = ni * 8 + 2 * (lane & 3);
      float a0 = sMadd[c], a1 = sMadd[c + 1];
      float p0 = __expf(sc[ni][0] + a0 - mr0) * il0;
      float p1 = __expf(sc[ni][1] + a1 - mr0) * il0;
      float p2 = __expf(sc[ni][2] + a0 - mr1) * il1;
      float p3 = __expf(sc[ni][3] + a1 - mr1) * il1;
      sP[rl * 68 + c] = p0;       sP[rl * 68 + c + 1] = p1;
      sP[(rl + 8) * 68 + c] = p2; sP[(rl + 8) * 68 + c + 1] = p3;
    }
    __syncwarp();
    if (attn) {  // coalesced attn tile store (each warp stores its own 16 rows)
      size_t abase = ((size_t)(b * H + h) * S + q0 + w * 16) * S + k0;
      for (int i = lane; i < 256; i += 32) {
        int r = i >> 4, c = (i & 15) * 4;
        float4 v = *(const float4*)&sP[(w * 16 + r) * 68 + c];
        *(float4*)&attn[abase + (size_t)r * S + c] = v;
      }
    }
    // ctx += P @ V
#pragma unroll
    for (int ks = 0; ks < 8; ks++) {
      int ar = w * 16 + (lane >> 2), ac = ks * 8 + (lane & 3);
      unsigned a0 = f2tf(sP[ar * 68 + ac]);
      unsigned a1 = f2tf(sP[(ar + 8) * 68 + ac]);
      unsigned a2 = f2tf(sP[ar * 68 + ac + 4]);
      unsigned a3 = f2tf(sP[(ar + 8) * 68 + ac + 4]);
#pragma unroll
      for (int ni = 0; ni < 8; ni++) {
        unsigned b0 = __float_as_uint(sV[(ks * 8 + (lane & 3)) * 72 + ni * 8 + (lane >> 2)]);
        unsigned b1 = __float_as_uint(sV[(ks * 8 + (lane & 3) + 4) * 72 + ni * 8 + (lane >> 2)]);
        mma_tf32(ctx[ni], a0, a1, a2, a3, b0, b1);
      }
    }
  }
  // write ctx: [B, S, D] with head offset
#pragma unroll
  for (int ni = 0; ni < 8; ni++) {
    int c = h * DH + ni * 8 + 2 * (lane & 3);
    size_t r0 = (size_t)(b * S) + q0 + w * 16 + (lane >> 2);
    *(float2*)&g_ctx[r0 * D + c] = make_float2(ctx[ni][0], ctx[ni][1]);
    *(float2*)&g_ctx[(r0 + 8) * D + c] = make_float2(ctx[ni][2], ctx[ni][3]);
  }
}

// ---------------- launch ----------------------------------------------------
extern "C" void kernel_launch(void* const* d_in, const int* in_sizes, int n_in,
                              void* d_out, int out_size) {
  using namespace cfg;
  (void)in_sizes; (void)n_in;
  const float* qs   = (const float*)d_in[0];
  const float* ksrc = (const float*)d_in[1];
  const float* vs   = (const float*)d_in[2];
  const void*  mask = d_in[3];
  const float* Wq = (const float*)d_in[4];
  const float* bq = (const float*)d_in[5];
  const float* Wk = (const float*)d_in[6];
  const float* bk = (const float*)d_in[7];
  const float* Wv = (const float*)d_in[8];
  const float* bv = (const float*)d_in[9];
  const float* Wo = (const float*)d_in[10];
  const float* bo = (const float*)d_in[11];

  void *pq, *pk, *pv, *pctx;
  cudaGetSymbolAddress(&pq, g_q);
  cudaGetSymbolAddress(&pk, g_k);
  cudaGetSymbolAddress(&pv, g_v);
  cudaGetSymbolAddress(&pctx, g_ctx);

  const size_t OUT_E = (size_t)B * S * D;             // 4,194,304
  const size_t ATTN_E = (size_t)B * H * S * S;        // 134,217,728
  float* out_ptr = (float*)d_out;
  float* attn_ptr = nullptr;
  size_t osz = (size_t)out_size;
  if (osz >= OUT_E + ATTN_E) {
    attn_ptr = out_ptr + OUT_E;                       // tuple (out, attn) flattened
  } else if (osz == ATTN_E) {                         // attn only
    attn_ptr = out_ptr;
    out_ptr = nullptr;
  }                                                   // else: out only

  const int SMEM1 = (2 * 64 * 68 + 64) * (int)sizeof(float);                 // 35 KB
  const int SMEM2 = (3 * 64 * 68 + 64 * 72 + 64) * (int)sizeof(float);       // ~69 KB
  cudaFuncSetAttribute(attn_pass2, cudaFuncAttributeMaxDynamicSharedMemorySize, SMEM2);

  detect_mask_kernel<<<1, 32>>>((const unsigned*)mask);

  dim3 pgrid(D / 64, MR / 128);  // (16, 32)
  proj_kernel<<<pgrid, 256>>>(qs,   Wq, bq, (float*)pq);
  proj_kernel<<<pgrid, 256>>>(ksrc, Wk, bk, (float*)pk);
  proj_kernel<<<pgrid, 256>>>(vs,   Wv, bv, (float*)pv);

  dim3 agrid(S / 64, H, B);  // (32, 16, 2)
  attn_pass1<<<agrid, 128, SMEM1>>>(mask);
  attn_pass2<<<agrid, 128, SMEM2>>>(mask, attn_ptr);

  proj_kernel<<<pgrid, 256>>>((const float*)pctx, Wo, bo,
                              out_ptr ? out_ptr : (float*)pq);
}

// round 2
// speedup vs baseline: 1.4614x; 1.4614x over previous
#include <cuda_runtime.h>
#include <cuda_bf16.h>
#include <cstdint>

#define DEVINL __device__ __forceinline__

namespace cfg {
constexpr int B = 2, S = 2048, D = 1024, H = 16, DH = 64;
constexpr int MR = B * S;  // 4096 rows for projection GEMMs
}

// ---------------- scratch (device globals; no allocation allowed) ----------
__device__ float g_q[(size_t)cfg::B * cfg::S * cfg::D];
__device__ float g_k[(size_t)cfg::B * cfg::S * cfg::D];
__device__ float g_v[(size_t)cfg::B * cfg::S * cfg::D];
__device__ float g_ctx[(size_t)cfg::B * cfg::S * cfg::D];
__device__ float g_m[cfg::B * cfg::H * cfg::S];
__device__ float g_l[cfg::B * cfg::H * cfg::S];
__device__ int   g_maskmode;   // 0=int32, 1=uint8, 2=float32

// ---------------- helpers ---------------------------------------------------
DEVINL unsigned f2tf(float x) {
  unsigned r;
  asm("cvt.rna.tf32.f32 %0, %1;" : "=r"(r) : "f"(x));
  return r;
}
DEVINL float f2tf_f(float x) { return __uint_as_float(f2tf(x)); }

DEVINL void mma_tf32(float c[4], unsigned a0, unsigned a1, unsigned a2, unsigned a3,
                     unsigned b0, unsigned b1) {
  asm volatile(
      "mma.sync.aligned.m16n8k8.row.col.f32.tf32.tf32.f32 "
      "{%0,%1,%2,%3}, {%4,%5,%6,%7}, {%8,%9}, {%0,%1,%2,%3};"
      : "+f"(c[0]), "+f"(c[1]), "+f"(c[2]), "+f"(c[3])
      : "r"(a0), "r"(a1), "r"(a2), "r"(a3), "r"(b0), "r"(b1));
}

DEVINL void mma_bf16(float c[4], unsigned a0, unsigned a1, unsigned a2, unsigned a3,
                     unsigned b0, unsigned b1) {
  asm volatile(
      "mma.sync.aligned.m16n8k16.row.col.f32.bf16.bf16.f32 "
      "{%0,%1,%2,%3}, {%4,%5,%6,%7}, {%8,%9}, {%0,%1,%2,%3};"
      : "+f"(c[0]), "+f"(c[1]), "+f"(c[2]), "+f"(c[3])
      : "r"(a0), "r"(a1), "r"(a2), "r"(a3), "r"(b0), "r"(b1));
}

// split (x,y) into bf16 hi pair and bf16 lo pair, each packed as b32 (x=low)
DEVINL void split_pair(float x, float y, unsigned& hi, unsigned& lo) {
  __nv_bfloat16 hx = __float2bfloat16_rn(x);
  __nv_bfloat16 hy = __float2bfloat16_rn(y);
  __nv_bfloat162 hp = __halves2bfloat162(hx, hy);
  hi = *reinterpret_cast<unsigned*>(&hp);
  float rx = x - __bfloat162float(hx);
  float ry = y - __bfloat162float(hy);
  __nv_bfloat162 lp = __floats2bfloat162_rn(rx, ry);
  lo = *reinterpret_cast<unsigned*>(&lp);
}

DEVINL int mask_on(const void* mask, int mode, int idx) {
  if (mode == 1) return ((const uint8_t*)mask)[idx] != 0;
  if (mode == 2) return ((const float*)mask)[idx] != 0.0f;
  return ((const int*)mask)[idx] != 0;
}

// ---------------- mask dtype detection -------------------------------------
__global__ void detect_mask_kernel(const unsigned* m) {
  int lane = threadIdx.x;
  int isf = 0, big = 0;
  for (int i = lane; i < 1024; i += 32) {
    unsigned v = m[i];
    if (v == 0x3F800000u) isf = 1;
    else if (v > 1u) big = 1;
  }
  isf = __any_sync(0xFFFFFFFFu, isf);
  big = __any_sync(0xFFFFFFFFu, big);
  if (lane == 0) g_maskmode = isf ? 2 : (big ? 1 : 0);
}

// ---------------- projection GEMM (bf16x3): Y = X @ W + bias ----------------
// BM=128, BN=64, BK=32. 256 threads = 8 warps (4x2), warp tile 32x32.
// hi/lo bf16 pairs stored adjacently as uint2 -> LDS.64 fetches both.
// 3 passes: Ahi*Bhi + Ahi*Blo + Alo*Bhi.
namespace pj {
constexpr int BM = 128, BN = 64, BK = 32;
constexpr int KP = BK / 2;   // 16 k-pairs
constexpr int ST = 20;       // uint2 stride per row (16 used + 4 pad)
constexpr int SA_U2 = 2 * BM * ST;            // double-buffered A
constexpr int SB_U2 = 2 * BN * ST;            // double-buffered B
constexpr int SMEM_BYTES = (SA_U2 + SB_U2) * 8;  // 60 KB
}

extern __shared__ char dyn_smem[];

__global__ void __launch_bounds__(256, 2) proj_bf16_kernel(
    const float* __restrict__ X, const float* __restrict__ W,
    const float* __restrict__ bias, float* __restrict__ Y) {
  using namespace pj;
  uint2* sA = reinterpret_cast<uint2*>(dyn_smem);          // [2][BM][ST]
  uint2* sB = sA + SA_U2;                                   // [2][BN][ST]

  const int N = cfg::D, K = cfg::D;
  const int m0 = blockIdx.y * BM, n0 = blockIdx.x * BN;
  const int tid = threadIdx.x, lane = tid & 31, warp = tid >> 5;
  const int wm0 = (warp >> 1) * 32, wn0 = (warp & 1) * 32;

  // global staging assignments
  const int ar = tid >> 1;            // 0..127
  const int ak = (tid & 1) * 16;      // 0 or 16
  const int bkp = tid >> 4;           // 0..15 (k-pair)
  const int bn = (tid & 15) * 4;      // 0..60

  float acc[2][4][4];
#pragma unroll
  for (int i = 0; i < 2; i++)
#pragma unroll
    for (int j = 0; j < 4; j++)
#pragma unroll
      for (int k = 0; k < 4; k++) acc[i][j][k] = 0.0f;

  float4 a4[4];
  float4 b4[2];

  auto load_regs = [&](int k0) {
    const float* ap = &X[(size_t)(m0 + ar) * K + k0 + ak];
#pragma unroll
    for (int t = 0; t < 4; t++) a4[t] = *(const float4*)(ap + t * 4);
    const float* bp0 = &W[(size_t)(k0 + 2 * bkp) * N + n0 + bn];
    const float* bp1 = &W[(size_t)(k0 + 2 * bkp + 1) * N + n0 + bn];
    b4[0] = *(const float4*)bp0;
    b4[1] = *(const float4*)bp1;
  };

  auto store_smem = [&](int buf) {
    const float* av = reinterpret_cast<const float*>(a4);
    uint2* sa = sA + (size_t)buf * BM * ST + (size_t)ar * ST + (ak >> 1);
#pragma unroll
    for (int j = 0; j < 8; j++) {
      unsigned hi, lo;
      split_pair(av[2 * j], av[2 * j + 1], hi, lo);
      sa[j] = make_uint2(hi, lo);
    }
    const float* b0v = reinterpret_cast<const float*>(&b4[0]);
    const float* b1v = reinterpret_cast<const float*>(&b4[1]);
#pragma unroll
    for (int j = 0; j < 4; j++) {
      unsigned hi, lo;
      split_pair(b0v[j], b1v[j], hi, lo);  // (k, k+1) pair for column n
      int n = bn + j;
      sB[(size_t)buf * BN * ST + (size_t)n * ST + (bkp ^ (n >> 3))] =
          make_uint2(hi, lo);
    }
  };

  auto compute = [&](int buf) {
    const uint2* sa = sA + (size_t)buf * BM * ST;
    const uint2* sb = sB + (size_t)buf * BN * ST;
#pragma unroll
    for (int ks = 0; ks < 2; ks++) {
      const int kpi = ks * 8 + (lane & 3);
      unsigned ahi[2][4], alo[2][4];
#pragma unroll
      for (int mi = 0; mi < 2; mi++) {
        int r = wm0 + mi * 16 + (lane >> 2);
        uint2 u0 = sa[(size_t)r * ST + kpi];
        uint2 u1 = sa[(size_t)(r + 8) * ST + kpi];
        uint2 u2 = sa[(size_t)r * ST + kpi + 4];
        uint2 u3 = sa[(size_t)(r + 8) * ST + kpi + 4];
        ahi[mi][0] = u0.x; ahi[mi][1] = u1.x; ahi[mi][2] = u2.x; ahi[mi][3] = u3.x;
        alo[mi][0] = u0.y; alo[mi][1] = u1.y; alo[mi][2] = u2.y; alo[mi][3] = u3.y;
      }
#pragma unroll
      for (int ni = 0; ni < 4; ni++) {
        int n = wn0 + ni * 8 + (lane >> 2);
        int sw = n >> 3;
        uint2 ub0 = sb[(size_t)n * ST + (kpi ^ sw)];
        uint2 ub1 = sb[(size_t)n * ST + ((kpi + 4) ^ sw)];
#pragma unroll
        for (int mi = 0; mi < 2; mi++) {
          mma_bf16(acc[mi][ni], ahi[mi][0], ahi[mi][1], ahi[mi][2], ahi[mi][3],
                   ub0.x, ub1.x);
          mma_bf16(acc[mi][ni], ahi[mi][0], ahi[mi][1], ahi[mi][2], ahi[mi][3],
                   ub0.y, ub1.y);
          mma_bf16(acc[mi][ni], alo[mi][0], alo[mi][1], alo[mi][2], alo[mi][3],
                   ub0.x, ub1.x);
        }
      }
    }
  };

  const int NIT = K / BK;  // 32
  load_regs(0);
  store_smem(0);
  __syncthreads();
  for (int t = 0; t < NIT; t++) {
    int buf = t & 1;
    if (t + 1 < NIT) load_regs((t + 1) * BK);
    compute(buf);
    if (t + 1 < NIT) store_smem(buf ^ 1);
    __syncthreads();
  }

#pragma unroll
  for (int mi = 0; mi < 2; mi++) {
#pragma unroll
    for (int ni = 0; ni < 4; ni++) {
      int r = m0 + wm0 + mi * 16 + (lane >> 2);
      int c = n0 + wn0 + ni * 8 + 2 * (lane & 3);
      float2 bb = *(const float2*)&bias[c];
      *(float2*)&Y[(size_t)r * N + c] =
          make_float2(acc[mi][ni][0] + bb.x, acc[mi][ni][1] + bb.y);
      *(float2*)&Y[(size_t)(r + 8) * N + c] =
          make_float2(acc[mi][ni][2] + bb.x, acc[mi][ni][3] + bb.y);
    }
  }
}

// ---------------- attention pass 1: per-row softmax stats (m, l) -----------
// grid (S/128, H, B), 256 threads (8 warps, warp w owns q-rows w*16..w*16+15)
__global__ void __launch_bounds__(256) attn_pass1(const void* __restrict__ mask) {
  using namespace cfg;
  float* smem = reinterpret_cast<float*>(dyn_smem);
  float* sQ = smem;                  // 128 x 68
  float* sK = sQ + 128 * 68;         // 64 x 68
  float* sMadd = sK + 64 * 68;       // 64
  const int q0 = blockIdx.x * 128, h = blockIdx.y, b = blockIdx.z;
  const int tid = threadIdx.x, lane = tid & 31, w = tid >> 5;
  const int mode = g_maskmode;

  for (int i = tid; i < 2048; i += 256) {
    int r = i >> 4, c = (i & 15) * 4;
    float4 v = *(const float4*)&g_q[((size_t)(b * S) + q0 + r) * D + h * DH + c];
    *(float4*)&sQ[r * 68 + c] =
        make_float4(f2tf_f(v.x * 0.125f), f2tf_f(v.y * 0.125f),
                    f2tf_f(v.z * 0.125f), f2tf_f(v.w * 0.125f));
  }

  float m_run[2] = {-1e30f, -1e30f}, l_run[2] = {0.0f, 0.0f};

  for (int kt = 0; kt < S / 64; kt++) {
    __syncthreads();
    const int k0 = kt * 64;
    for (int i = tid; i < 1024; i += 256) {
      int r = i >> 4, c = (i & 15) * 4;
      float4 v = *(const float4*)&g_k[((size_t)(b * S) + k0 + r) * D + h * DH + c];
      *(float4*)&sK[r * 68 + c] =
          make_float4(f2tf_f(v.x), f2tf_f(v.y), f2tf_f(v.z), f2tf_f(v.w));
    }
    if (tid < 64) sMadd[tid] = mask_on(mask, mode, b * S + k0 + tid) ? 0.0f : -1e30f;
    __syncthreads();

    float sc[8][4];
#pragma unroll
    for (int ni = 0; ni < 8; ni++) { sc[ni][0] = sc[ni][1] = sc[ni][2] = sc[ni][3] = 0.0f; }
#pragma unroll
    for (int ks = 0; ks < 8; ks++) {
      int ar = w * 16 + (lane >> 2), ac = ks * 8 + (lane & 3);
      unsigned a0 = __float_as_uint(sQ[ar * 68 + ac]);
      unsigned a1 = __float_as_uint(sQ[(ar + 8) * 68 + ac]);
      unsigned a2 = __float_as_uint(sQ[ar * 68 + ac + 4]);
      unsigned a3 = __float_as_uint(sQ[(ar + 8) * 68 + ac + 4]);
#pragma unroll
      for (int ni = 0; ni < 8; ni++) {
        int bn = ni * 8 + (lane >> 2), bd = ks * 8 + (lane & 3);
        unsigned b0 = __float_as_uint(sK[bn * 68 + bd]);
        unsigned b1 = __float_as_uint(sK[bn * 68 + bd + 4]);
        mma_tf32(sc[ni], a0, a1, a2, a3, b0, b1);
      }
    }
    float tmax0 = -1e30f, tmax1 = -1e30f;
#pragma unroll
    for (int ni = 0; ni < 8; ni++) {
      int c = ni * 8 + 2 * (lane & 3);
      float a0 = sMadd[c], a1 = sMadd[c + 1];
      sc[ni][0] += a0; sc[ni][1] += a1; sc[ni][2] += a0; sc[ni][3] += a1;
      tmax0 = fmaxf(tmax0, fmaxf(sc[ni][0], sc[ni][1]));
      tmax1 = fmaxf(tmax1, fmaxf(sc[ni][2], sc[ni][3]));
    }
    tmax0 = fmaxf(tmax0, __shfl_xor_sync(0xFFFFFFFFu, tmax0, 1));
    tmax0 = fmaxf(tmax0, __shfl_xor_sync(0xFFFFFFFFu, tmax0, 2));
    tmax1 = fmaxf(tmax1, __shfl_xor_sync(0xFFFFFFFFu, tmax1, 1));
    tmax1 = fmaxf(tmax1, __shfl_xor_sync(0xFFFFFFFFu, tmax1, 2));
    float mn0 = fmaxf(m_run[0], tmax0), mn1 = fmaxf(m_run[1], tmax1);
    float ts0 = 0.0f, ts1 = 0.0f;
#pragma unroll
    for (int ni = 0; ni < 8; ni++) {
      ts0 += __expf(sc[ni][0] - mn0) + __expf(sc[ni][1] - mn0);
      ts1 += __expf(sc[ni][2] - mn1) + __expf(sc[ni][3] - mn1);
    }
    ts0 += __shfl_xor_sync(0xFFFFFFFFu, ts0, 1);
    ts0 += __shfl_xor_sync(0xFFFFFFFFu, ts0, 2);
    ts1 += __shfl_xor_sync(0xFFFFFFFFu, ts1, 1);
    ts1 += __shfl_xor_sync(0xFFFFFFFFu, ts1, 2);
    l_run[0] = l_run[0] * __expf(m_run[0] - mn0) + ts0; m_run[0] = mn0;
    l_run[1] = l_run[1] * __expf(m_run[1] - mn1) + ts1; m_run[1] = mn1;
  }
  if ((lane & 3) == 0) {
    size_t base = (size_t)(b * H + h) * S;
    int r = q0 + w * 16 + (lane >> 2);
    g_m[base + r] = m_run[0];     g_l[base + r] = l_run[0];
    g_m[base + r + 8] = m_run[1]; g_l[base + r + 8] = l_run[1];
  }
}

// ---------------- attention pass 2: attn write + ctx = P @ V ---------------
__global__ void __launch_bounds__(256) attn_pass2(const void* __restrict__ mask,
                                                  float* __restrict__ attn) {
  using namespace cfg;
  float* smem = reinterpret_cast<float*>(dyn_smem);
  float* sQ = smem;                   // 128 x 68
  float* sK = sQ + 128 * 68;          // 64 x 68
  float* sV = sK + 64 * 68;           // 64 x 72
  float* sP = sV + 64 * 72;           // 128 x 68
  float* sMadd = sP + 128 * 68;       // 64
  const int q0 = blockIdx.x * 128, h = blockIdx.y, b = blockIdx.z;
  const int tid = threadIdx.x, lane = tid & 31, w = tid >> 5;
  const int mode = g_maskmode;

  for (int i = tid; i < 2048; i += 256) {
    int r = i >> 4, c = (i & 15) * 4;
    float4 v = *(const float4*)&g_q[((size_t)(b * S) + q0 + r) * D + h * DH + c];
    *(float4*)&sQ[r * 68 + c] =
        make_float4(f2tf_f(v.x * 0.125f), f2tf_f(v.y * 0.125f),
                    f2tf_f(v.z * 0.125f), f2tf_f(v.w * 0.125f));
  }

  size_t mbase = (size_t)(b * H + h) * S;
  int myrow = q0 + w * 16 + (lane >> 2);
  float mr0 = g_m[mbase + myrow], mr1 = g_m[mbase + myrow + 8];
  float il0 = 1.0f / g_l[mbase + myrow], il1 = 1.0f / g_l[mbase + myrow + 8];

  float ctx[8][4];
#pragma unroll
  for (int ni = 0; ni < 8; ni++) { ctx[ni][0] = ctx[ni][1] = ctx[ni][2] = ctx[ni][3] = 0.0f; }

  for (int kt = 0; kt < S / 64; kt++) {
    __syncthreads();
    const int k0 = kt * 64;
    for (int i = tid; i < 1024; i += 256) {
      int r = i >> 4, c = (i & 15) * 4;
      float4 vk = *(const float4*)&g_k[((size_t)(b * S) + k0 + r) * D + h * DH + c];
      *(float4*)&sK[r * 68 + c] =
          make_float4(f2tf_f(vk.x), f2tf_f(vk.y), f2tf_f(vk.z), f2tf_f(vk.w));
      float4 vv = *(const float4*)&g_v[((size_t)(b * S) + k0 + r) * D + h * DH + c];
      *(float4*)&sV[r * 72 + c] =
          make_float4(f2tf_f(vv.x), f2tf_f(vv.y), f2tf_f(vv.z), f2tf_f(vv.w));
    }
    if (tid < 64) sMadd[tid] = mask_on(mask, mode, b * S + k0 + tid) ? 0.0f : -1e30f;
    __syncthreads();

    float sc[8][4];
#pragma unroll
    for (int ni = 0; ni < 8; ni++) { sc[ni][0] = sc[ni][1] = sc[ni][2] = sc[ni][3] = 0.0f; }
#pragma unroll
    for (int ks = 0; ks < 8; ks++) {
      int ar = w * 16 + (lane >> 2), ac = ks * 8 + (lane & 3);
      unsigned a0 = __float_as_uint(sQ[ar * 68 + ac]);
      unsigned a1 = __float_as_uint(sQ[(ar + 8) * 68 + ac]);
      unsigned a2 = __float_as_uint(sQ[ar * 68 + ac + 4]);
      unsigned a3 = __float_as_uint(sQ[(ar + 8) * 68 + ac + 4]);
#pragma unroll
      for (int ni = 0; ni < 8; ni++) {
        int bn = ni * 8 + (lane >> 2), bd = ks * 8 + (lane & 3);
        unsigned b0 = __float_as_uint(sK[bn * 68 + bd]);
        unsigned b1 = __float_as_uint(sK[bn * 68 + bd + 4]);
        mma_tf32(sc[ni], a0, a1, a2, a3, b0, b1);
      }
    }
    // p = exp(s + maskadd - m) / l; stage into sP (warp-private rows)
    const int rl = w * 16 + (lane >> 2);
#pragma unroll
    for (int ni = 0; ni < 8; ni++) {
      int c = ni * 8 + 2 * (lane & 3);
      float a0 = sMadd[c], a1 = sMadd[c + 1];
      float p0 = __expf(sc[ni][0] + a0 - mr0) * il0;
      float p1 = __expf(sc[ni][1] + a1 - mr0) * il0;
      float p2 = __expf(sc[ni][2] + a0 - mr1) * il1;
      float p3 = __expf(sc[ni][3] + a1 - mr1) * il1;
      sP[rl * 68 + c] = p0;       sP[rl * 68 + c + 1] = p1;
      sP[(rl + 8) * 68 + c] = p2; sP[(rl + 8) * 68 + c + 1] = p3;
    }
    __syncwarp();
    if (attn) {  // coalesced attn tile store (each warp stores its own 16 rows)
      size_t abase = ((size_t)(b * H + h) * S + q0 + w * 16) * S + k0;
      for (int i = lane; i < 256; i += 32) {
        int r = i >> 4, c = (i & 15) * 4;
        float4 v = *(const float4*)&sP[(w * 16 + r) * 68 + c];
        *(float4*)&attn[abase + (size_t)r * S + c] = v;
      }
    }
    // ctx += P @ V
#pragma unroll
    for (int ks = 0; ks < 8; ks++) {
      int ar = w * 16 + (lane >> 2), ac = ks * 8 + (lane & 3);
      unsigned a0 = f2tf(sP[ar * 68 + ac]);
      unsigned a1 = f2tf(sP[(ar + 8) * 68 + ac]);
      unsigned a2 = f2tf(sP[ar * 68 + ac + 4]);
      unsigned a3 = f2tf(sP[(ar + 8) * 68 + ac + 4]);
#pragma unroll
      for (int ni = 0; ni < 8; ni++) {
        unsigned b0 = __float_as_uint(sV[(ks * 8 + (lane & 3)) * 72 + ni * 8 + (lane >> 2)]);
        unsigned b1 = __float_as_uint(sV[(ks * 8 + (lane & 3) + 4) * 72 + ni * 8 + (lane >> 2)]);
        mma_tf32(ctx[ni], a0, a1, a2, a3, b0, b1);
      }
    }
  }
  // write ctx: [B, S, D] with head offset
#pragma unroll
  for (int ni = 0; ni < 8; ni++) {
    int c = h * DH + ni * 8 + 2 * (lane & 3);
    size_t r0 = (size_t)(b * S) + q0 + w * 16 + (lane >> 2);
    *(float2*)&g_ctx[r0 * D + c] = make_float2(ctx[ni][0], ctx[ni][1]);
    *(float2*)&g_ctx[(r0 + 8) * D + c] = make_float2(ctx[ni][2], ctx[ni][3]);
  }
}

// ---------------- launch ----------------------------------------------------
extern "C" void kernel_launch(void* const* d_in, const int* in_sizes, int n_in,
                              void* d_out, int out_size) {
  using namespace cfg;
  (void)in_sizes; (void)n_in;
  const float* qs   = (const float*)d_in[0];
  const float* ksrc = (const float*)d_in[1];
  const float* vs   = (const float*)d_in[2];
  const void*  mask = d_in[3];
  const float* Wq = (const float*)d_in[4];
  const float* bq = (const float*)d_in[5];
  const float* Wk = (const float*)d_in[6];
  const float* bk = (const float*)d_in[7];
  const float* Wv = (const float*)d_in[8];
  const float* bv = (const float*)d_in[9];
  const float* Wo = (const float*)d_in[10];
  const float* bo = (const float*)d_in[11];

  void *pq, *pk, *pv, *pctx;
  cudaGetSymbolAddress(&pq, g_q);
  cudaGetSymbolAddress(&pk, g_k);
  cudaGetSymbolAddress(&pv, g_v);
  cudaGetSymbolAddress(&pctx, g_ctx);

  const size_t OUT_E = (size_t)B * S * D;             // 4,194,304
  const size_t ATTN_E = (size_t)B * H * S * S;        // 134,217,728
  float* out_ptr = (float*)d_out;
  float* attn_ptr = nullptr;
  size_t osz = (size_t)out_size;
  if (osz >= OUT_E + ATTN_E) {
    attn_ptr = out_ptr + OUT_E;                       // tuple (out, attn) flattened
  } else if (osz == ATTN_E) {                         // attn only
    attn_ptr = out_ptr;
    out_ptr = nullptr;
  }                                                   // else: out only

  const int SMEMP = pj::SMEM_BYTES;                                          // 60 KB
  const int SMEM1 = (128 * 68 + 64 * 68 + 64) * (int)sizeof(float);          // ~52 KB
  const int SMEM2 = (128 * 68 + 64 * 68 + 64 * 72 + 128 * 68 + 64) * (int)sizeof(float);  // ~106 KB
  static int attr_done = 0;
  if (!attr_done) {
    cudaFuncSetAttribute(proj_bf16_kernel, cudaFuncAttributeMaxDynamicSharedMemorySize, SMEMP);
    cudaFuncSetAttribute(attn_pass1, cudaFuncAttributeMaxDynamicSharedMemorySize, SMEM1);
    cudaFuncSetAttribute(attn_pass2, cudaFuncAttributeMaxDynamicSharedMemorySize, SMEM2);
    attr_done = 1;
  }

  detect_mask_kernel<<<1, 32>>>((const unsigned*)mask);

  dim3 pgrid(D / pj::BN, MR / pj::BM);  // (16, 32)
  proj_bf16_kernel<<<pgrid, 256, SMEMP>>>(qs,   Wq, bq, (float*)pq);
  proj_bf16_kernel<<<pgrid, 256, SMEMP>>>(ksrc, Wk, bk, (float*)pk);
  proj_bf16_kernel<<<pgrid, 256, SMEMP>>>(vs,   Wv, bv, (float*)pv);

  dim3 agrid(S / 128, H, B);  // (16, 16, 2)
  attn_pass1<<<agrid, 256, SMEM1>>>(mask);
  attn_pass2<<<agrid, 256, SMEM2>>>(mask, attn_ptr);

  proj_bf16_kernel<<<pgrid, 256, SMEMP>>>((const float*)pctx, Wo, bo,
                                          out_ptr ? out_ptr : (float*)pq);
}

// round 5
// speedup vs baseline: 1.6083x; 1.1005x over previous
#include <cuda_runtime.h>
#include <cuda_bf16.h>
#include <cstdint>

#define DEVINL __device__ __forceinline__

namespace cfg {
constexpr int B = 2, S = 2048, D = 1024, H = 16, DH = 64;
constexpr int MR = B * S;   // 4096 rows
constexpr int KH = D / 2;   // 512 k-pairs
}

// ---------------- scratch (device globals; no allocation allowed) ----------
__device__ float g_q[(size_t)cfg::B * cfg::S * cfg::D];
__device__ float g_k[(size_t)cfg::B * cfg::S * cfg::D];
__device__ float g_v[(size_t)cfg::B * cfg::S * cfg::D];
__device__ float g_ctx[(size_t)cfg::B * cfg::S * cfg::D];
__device__ float g_m[cfg::B * cfg::H * cfg::S];
__device__ float g_l[cfg::B * cfg::H * cfg::S];
__device__ int   g_maskmode;

// packed bf16 (hi,lo) operands
__device__ __align__(256) uint4 g_xs4[(size_t)3 * cfg::MR * cfg::D / 4];  // q,k,v inputs
__device__ __align__(256) uint4 g_cs4[(size_t)cfg::MR * cfg::D / 4];      // ctx
__device__ __align__(256) uint4 g_wT4[(size_t)4 * cfg::D * cfg::D / 4];   // Wq,Wk,Wv,Wo transposed

extern __shared__ char dyn_smem[];

// ---------------- helpers ---------------------------------------------------
DEVINL unsigned f2tf(float x) {
  unsigned r;
  asm("cvt.rna.tf32.f32 %0, %1;" : "=r"(r) : "f"(x));
  return r;
}
DEVINL float f2tf_f(float x) { return __uint_as_float(f2tf(x)); }

DEVINL void mma_tf32(float c[4], unsigned a0, unsigned a1, unsigned a2, unsigned a3,
                     unsigned b0, unsigned b1) {
  asm volatile(
      "mma.sync.aligned.m16n8k8.row.col.f32.tf32.tf32.f32 "
      "{%0,%1,%2,%3}, {%4,%5,%6,%7}, {%8,%9}, {%0,%1,%2,%3};"
      : "+f"(c[0]), "+f"(c[1]), "+f"(c[2]), "+f"(c[3])
      : "r"(a0), "r"(a1), "r"(a2), "r"(a3), "r"(b0), "r"(b1));
}

DEVINL void mma_bf16(float c[4], unsigned a0, unsigned a1, unsigned a2, unsigned a3,
                     unsigned b0, unsigned b1) {
  asm volatile(
      "mma.sync.aligned.m16n8k16.row.col.f32.bf16.bf16.f32 "
      "{%0,%1,%2,%3}, {%4,%5,%6,%7}, {%8,%9}, {%0,%1,%2,%3};"
      : "+f"(c[0]), "+f"(c[1]), "+f"(c[2]), "+f"(c[3])
      : "r"(a0), "r"(a1), "r"(a2), "r"(a3), "r"(b0), "r"(b1));
}

DEVINL void split_pair(float x, float y, unsigned& hi, unsigned& lo) {
  __nv_bfloat16 hx = __float2bfloat16_rn(x);
  __nv_bfloat16 hy = __float2bfloat16_rn(y);
  __nv_bfloat162 hp = __halves2bfloat162(hx, hy);
  hi = *reinterpret_cast<unsigned*>(&hp);
  float rx = x - __bfloat162float(hx);
  float ry = y - __bfloat162float(hy);
  __nv_bfloat162 lp = __floats2bfloat162_rn(rx, ry);
  lo = *reinterpret_cast<unsigned*>(&lp);
}

DEVINL int mask_on(const void* mask, int mode, int idx) {
  if (mode == 1) return ((const uint8_t*)mask)[idx] != 0;
  if (mode == 2) return ((const float*)mask)[idx] != 0.0f;
  return ((const int*)mask)[idx] != 0;
}

DEVINL void cpa16(uint32_t dst, const void* src) {
  asm volatile("cp.async.cg.shared.global [%0], [%1], 16;\n" :: "r"(dst), "l"(src));
}
DEVINL void cp_commit() { asm volatile("cp.async.commit_group;\n" ::); }

// ---------------- mask dtype detection -------------------------------------
__global__ void detect_mask_kernel(const unsigned* m) {
  int lane = threadIdx.x;
  int isf = 0, big = 0;
  for (int i = lane; i < 1024; i += 32) {
    unsigned v = m[i];
    if (v == 0x3F800000u) isf = 1;
    else if (v > 1u) big = 1;
  }
  isf = __any_sync(0xFFFFFFFFu, isf);
  big = __any_sync(0xFFFFFFFFu, big);
  if (lane == 0) g_maskmode = isf ? 2 : (big ? 1 : 0);
}

// ---------------- operand preparation ---------------------------------------
struct Ptr3 { const float* x[3]; };

// split [M,D] fp32 -> [M, KH] packed (hi,lo) uint2 pairs; one float4 per thread
__global__ void __launch_bounds__(256) split_x3_kernel(Ptr3 src, uint4* dst) {
  constexpr size_t PER_Z = (size_t)cfg::MR * cfg::D / 4;  // uint4 per input
  int z = blockIdx.z;
  size_t i = (size_t)blockIdx.x * blockDim.x + threadIdx.x;  // < PER_Z
  float4 v = ((const float4*)src.x[z])[i];
  unsigned h0, l0, h1, l1;
  split_pair(v.x, v.y, h0, l0);
  split_pair(v.z, v.w, h1, l1);
  dst[(size_t)z * PER_Z + i] = make_uint4(h0, l0, h1, l1);
}

struct Ptr4 { const float* w[4]; };

// W[K,N] fp32 -> WT[N, KH] packed (hi,lo) uint2, via smem transpose
__global__ void __launch_bounds__(256) split_wT4_kernel(Ptr4 src, uint2* dst) {
  using namespace cfg;
  __shared__ float sw[64][65];
  const float* W = src.w[blockIdx.z];
  const int k0 = blockIdx.y * 64, n0 = blockIdx.x * 64;
  const int tid = threadIdx.x;
  for (int i = tid; i < 64 * 64; i += 256) {
    int r = i >> 6, c = i & 63;
    sw[r][c] = W[(size_t)(k0 + r) * D + n0 + c];
  }
  __syncthreads();
  uint2* out = dst + (size_t)blockIdx.z * D * KH;
  for (int i = tid; i < 64 * 32; i += 256) {
    int n = i >> 5, kp = i & 31;
    unsigned hi, lo;
    split_pair(sw[2 * kp][n], sw[2 * kp + 1][n], hi, lo);
    out[(size_t)(n0 + n) * KH + (k0 >> 1) + kp] = make_uint2(hi, lo);
  }
}

// ---------------- projection GEMM v2 (cp.async, pre-split bf16x3) -----------
namespace pj {
constexpr int BM = 128, BN = 64, BK = 32, KP = 16, ST = 20;
constexpr int STG = (BM + BN) * ST;   // uint2 per stage (3840)
constexpr int NS = 3;
constexpr int SMEM_BYTES = NS * STG * 8;  // 92160
}

struct ProjJob { const uint2* A; const uint2* Bt; const float* bias; float* Y; int mode; };
struct ProjJobs { ProjJob j[3]; };

__global__ void __launch_bounds__(256, 2) proj2_kernel(ProjJobs jobs) {
  using namespace pj;
  using namespace cfg;
  const ProjJob jb = jobs.j[blockIdx.z];
  uint2* smem_u2 = reinterpret_cast<uint2*>(dyn_smem);
  const uint32_t sbase = (uint32_t)__cvta_generic_to_shared(dyn_smem);

  const int m0 = blockIdx.y * BM, n0 = blockIdx.x * BN;
  const int tid = threadIdx.x, lane = tid & 31, warp = tid >> 5;
  const int wm0 = (warp >> 1) * 32, wn0 = (warp & 1) * 32;

  float acc[2][4][4];
#pragma unroll
  for (int i = 0; i < 2; i++)
#pragma unroll
    for (int j = 0; j < 4; j++)
#pragma unroll
      for (int k = 0; k < 4; k++) acc[i][j][k] = 0.0f;

  auto issue = [&](int stage, int kt) {
    const uint2* Ag = jb.A + (size_t)m0 * KH + (size_t)kt * KP;
#pragma unroll
    for (int j = 0; j < 4; j++) {
      int i = tid + j * 256;                 // 0..1023
      int r = i >> 3, c = (i & 7) * 2;
      cpa16(sbase + (uint32_t)((stage * STG + r * ST + c) * 8),
            Ag + (size_t)r * KH + c);
    }
    const uint2* Bg = jb.Bt + (size_t)n0 * KH + (size_t)kt * KP;
#pragma unroll
    for (int j = 0; j < 2; j++) {
      int i = tid + j * 256;                 // 0..511
      int r = i >> 3, c = (i & 7) * 2;
      cpa16(sbase + (uint32_t)((stage * STG + BM * ST + r * ST + c) * 8),
            Bg + (size_t)r * KH + c);
    }
    cp_commit();
  };

  constexpr int NIT = cfg::D / BK;  // 32
  issue(0, 0);
  issue(1, 1);
  for (int t = 0; t < NIT; t++) {
    if (t == NIT - 1) asm volatile("cp.async.wait_group 0;\n" ::);
    else              asm volatile("cp.async.wait_group 1;\n" ::);
    __syncthreads();
    if (t + 2 < NIT) issue((t + 2) % NS, t + 2);

    const uint2* sa = smem_u2 + (size_t)(t % NS) * STG;
    const uint2* sb = sa + BM * ST;
#pragma unroll
    for (int ks = 0; ks < 2; ks++) {
      const int kpi = ks * 8 + (lane & 3);
      unsigned ahi[2][4], alo[2][4];
#pragma unroll
      for (int mi = 0; mi < 2; mi++) {
        int r = wm0 + mi * 16 + (lane >> 2);
        uint2 u0 = sa[r * ST + kpi];
        uint2 u1 = sa[(r + 8) * ST + kpi];
        uint2 u2 = sa[r * ST + kpi + 4];
        uint2 u3 = sa[(r + 8) * ST + kpi + 4];
        ahi[mi][0] = u0.x; ahi[mi][1] = u1.x; ahi[mi][2] = u2.x; ahi[mi][3] = u3.x;
        alo[mi][0] = u0.y; alo[mi][1] = u1.y; alo[mi][2] = u2.y; alo[mi][3] = u3.y;
      }
#pragma unroll
      for (int ni = 0; ni < 4; ni++) {
        int n = wn0 + ni * 8 + (lane >> 2);
        uint2 ub0 = sb[n * ST + kpi];
        uint2 ub1 = sb[n * ST + kpi + 4];
#pragma unroll
        for (int mi = 0; mi < 2; mi++) {
          mma_bf16(acc[mi][ni], ahi[mi][0], ahi[mi][1], ahi[mi][2], ahi[mi][3],
                   ub0.x, ub1.x);
          mma_bf16(acc[mi][ni], ahi[mi][0], ahi[mi][1], ahi[mi][2], ahi[mi][3],
                   ub0.y, ub1.y);
          mma_bf16(acc[mi][ni], alo[mi][0], alo[mi][1], alo[mi][2], alo[mi][3],
                   ub0.x, ub1.x);
        }
      }
    }
  }

  const int mode = jb.mode;
#pragma unroll
  for (int mi = 0; mi < 2; mi++) {
#pragma unroll
    for (int ni = 0; ni < 4; ni++) {
      int r = m0 + wm0 + mi * 16 + (lane >> 2);
      int c = n0 + wn0 + ni * 8 + 2 * (lane & 3);
      float2 bb = *(const float2*)&jb.bias[c];
      float v0 = acc[mi][ni][0] + bb.x, v1 = acc[mi][ni][1] + bb.y;
      float v2 = acc[mi][ni][2] + bb.x, v3 = acc[mi][ni][3] + bb.y;
      if (mode == 2) {
        v0 = f2tf_f(v0 * 0.125f); v1 = f2tf_f(v1 * 0.125f);
        v2 = f2tf_f(v2 * 0.125f); v3 = f2tf_f(v3 * 0.125f);
      } else if (mode == 1) {
        v0 = f2tf_f(v0); v1 = f2tf_f(v1); v2 = f2tf_f(v2); v3 = f2tf_f(v3);
      }
      *(float2*)&jb.Y[(size_t)r * cfg::D + c] = make_float2(v0, v1);
      *(float2*)&jb.Y[(size_t)(r + 8) * cfg::D + c] = make_float2(v2, v3);
    }
  }
}

// ---------------- attention pass 1: per-row softmax stats (m, l) -----------
__global__ void __launch_bounds__(256) attn_pass1(const void* __restrict__ mask) {
  using namespace cfg;
  float* smem = reinterpret_cast<float*>(dyn_smem);
  float* sQ = smem;                  // 128 x 68
  float* sK = sQ + 128 * 68;         // 64 x 68
  float* sMadd = sK + 64 * 68;       // 64
  const int q0 = blockIdx.x * 128, h = blockIdx.y, b = blockIdx.z;
  const int tid = threadIdx.x, lane = tid & 31, w = tid >> 5;
  const int mode = g_maskmode;

  for (int i = tid; i < 2048; i += 256) {
    int r = i >> 4, c = (i & 15) * 4;
    *(float4*)&sQ[r * 68 + c] =
        *(const float4*)&g_q[((size_t)(b * S) + q0 + r) * D + h * DH + c];
  }

  float m_run[2] = {-1e30f, -1e30f}, l_run[2] = {0.0f, 0.0f};

  for (int kt = 0; kt < S / 64; kt++) {
    __syncthreads();
    const int k0 = kt * 64;
    for (int i = tid; i < 1024; i += 256) {
      int r = i >> 4, c = (i & 15) * 4;
      *(float4*)&sK[r * 68 + c] =
          *(const float4*)&g_k[((size_t)(b * S) + k0 + r) * D + h * DH + c];
    }
    if (tid < 64) sMadd[tid] = mask_on(mask, mode, b * S + k0 + tid) ? 0.0f : -1e30f;
    __syncthreads();

    float sc[8][4];
#pragma unroll
    for (int ni = 0; ni < 8; ni++) { sc[ni][0] = sc[ni][1] = sc[ni][2] = sc[ni][3] = 0.0f; }
#pragma unroll
    for (int ks = 0; ks < 8; ks++) {
      int ar = w * 16 + (lane >> 2), ac = ks * 8 + (lane & 3);
      unsigned a0 = __float_as_uint(sQ[ar * 68 + ac]);
      unsigned a1 = __float_as_uint(sQ[(ar + 8) * 68 + ac]);
      unsigned a2 = __float_as_uint(sQ[ar * 68 + ac + 4]);
      unsigned a3 = __float_as_uint(sQ[(ar + 8) * 68 + ac + 4]);
#pragma unroll
      for (int ni = 0; ni < 8; ni++) {
        int bn = ni * 8 + (lane >> 2), bd = ks * 8 + (lane & 3);
        unsigned b0 = __float_as_uint(sK[bn * 68 + bd]);
        unsigned b1 = __float_as_uint(sK[bn * 68 + bd + 4]);
        mma_tf32(sc[ni], a0, a1, a2, a3, b0, b1);
      }
    }
    float tmax0 = -1e30f, tmax1 = -1e30f;
#pragma unroll
    for (int ni = 0; ni < 8; ni++) {
      int c = ni * 8 + 2 * (lane & 3);
      float a0 = sMadd[c], a1 = sMadd[c + 1];
      sc[ni][0] += a0; sc[ni][1] += a1; sc[ni][2] += a0; sc[ni][3] += a1;
      tmax0 = fmaxf(tmax0, fmaxf(sc[ni][0], sc[ni][1]));
      tmax1 = fmaxf(tmax1, fmaxf(sc[ni][2], sc[ni][3]));
    }
    tmax0 = fmaxf(tmax0, __shfl_xor_sync(0xFFFFFFFFu, tmax0, 1));
    tmax0 = fmaxf(tmax0, __shfl_xor_sync(0xFFFFFFFFu, tmax0, 2));
    tmax1 = fmaxf(tmax1, __shfl_xor_sync(0xFFFFFFFFu, tmax1, 1));
    tmax1 = fmaxf(tmax1, __shfl_xor_sync(0xFFFFFFFFu, tmax1, 2));
    float mn0 = fmaxf(m_run[0], tmax0), mn1 = fmaxf(m_run[1], tmax1);
    float ts0 = 0.0f, ts1 = 0.0f;
#pragma unroll
    for (int ni = 0; ni < 8; ni++) {
      ts0 += __expf(sc[ni][0] - mn0) + __expf(sc[ni][1] - mn0);
      ts1 += __expf(sc[ni][2] - mn1) + __expf(sc[ni][3] - mn1);
    }
    ts0 += __shfl_xor_sync(0xFFFFFFFFu, ts0, 1);
    ts0 += __shfl_xor_sync(0xFFFFFFFFu, ts0, 2);
    ts1 += __shfl_xor_sync(0xFFFFFFFFu, ts1, 1);
    ts1 += __shfl_xor_sync(0xFFFFFFFFu, ts1, 2);
    l_run[0] = l_run[0] * __expf(m_run[0] - mn0) + ts0; m_run[0] = mn0;
    l_run[1] = l_run[1] * __expf(m_run[1] - mn1) + ts1; m_run[1] = mn1;
  }
  if ((lane & 3) == 0) {
    size_t base = (size_t)(b * H + h) * S;
    int r = q0 + w * 16 + (lane >> 2);
    g_m[base + r] = m_run[0];     g_l[base + r] = l_run[0];
    g_m[base + r + 8] = m_run[1]; g_l[base + r + 8] = l_run[1];
  }
}

// ---------------- attention pass 2: attn write + ctx = P @ V ---------------
__global__ void __launch_bounds__(256) attn_pass2(const void* __restrict__ mask,
                                                  float* __restrict__ attn) {
  using namespace cfg;
  float* smem = reinterpret_cast<float*>(dyn_smem);
  float* sQ = smem;                   // 128 x 68
  float* sK = sQ + 128 * 68;          // 64 x 68
  float* sV = sK + 64 * 68;           // 64 x 72
  float* sP = sV + 64 * 72;           // 128 x 68
  float* sMadd = sP + 128 * 68;       // 64
  const int q0 = blockIdx.x * 128, h = blockIdx.y, b = blockIdx.z;
  const int tid = threadIdx.x, lane = tid & 31, w = tid >> 5;
  const int mode = g_maskmode;

  for (int i = tid; i < 2048; i += 256) {
    int r = i >> 4, c = (i & 15) * 4;
    *(float4*)&sQ[r * 68 + c] =
        *(const float4*)&g_q[((size_t)(b * S) + q0 + r) * D + h * DH + c];
  }

  size_t mbase = (size_t)(b * H + h) * S;
  int myrow = q0 + w * 16 + (lane >> 2);
  float mr0 = g_m[mbase + myrow], mr1 = g_m[mbase + myrow + 8];
  float il0 = 1.0f / g_l[mbase + myrow], il1 = 1.0f / g_l[mbase + myrow + 8];

  float ctx[8][4];
#pragma unroll
  for (int ni = 0; ni < 8; ni++) { ctx[ni][0] = ctx[ni][1] = ctx[ni][2] = ctx[ni][3] = 0.0f; }

  for (int kt = 0; kt < S / 64; kt++) {
    __syncthreads();
    const int k0 = kt * 64;
    for (int i = tid; i < 1024; i += 256) {
      int r = i >> 4, c = (i & 15) * 4;
      *(float4*)&sK[r * 68 + c] =
          *(const float4*)&g_k[((size_t)(b * S) + k0 + r) * D + h * DH + c];
      *(float4*)&sV[r * 72 + c] =
          *(const float4*)&g_v[((size_t)(b * S) + k0 + r) * D + h * DH + c];
    }
    if (tid < 64) sMadd[tid] = mask_on(mask, mode, b * S + k0 + tid) ? 0.0f : -1e30f;
    __syncthreads();

    float sc[8][4];
#pragma unroll
    for (int ni = 0; ni < 8; ni++) { sc[ni][0] = sc[ni][1] = sc[ni][2] = sc[ni][3] = 0.0f; }
#pragma unroll
    for (int ks = 0; ks < 8; ks++) {
      int ar = w * 16 + (lane >> 2), ac = ks * 8 + (lane & 3);
      unsigned a0 = __float_as_uint(sQ[ar * 68 + ac]);
      unsigned a1 = __float_as_uint(sQ[(ar + 8) * 68 + ac]);
      unsigned a2 = __float_as_uint(sQ[ar * 68 + ac + 4]);
      unsigned a3 = __float_as_uint(sQ[(ar + 8) * 68 + ac + 4]);
#pragma unroll
      for (int ni = 0; ni < 8; ni++) {
        int bn = ni * 8 + (lane >> 2), bd = ks * 8 + (lane & 3);
        unsigned b0 = __float_as_uint(sK[bn * 68 + bd]);
        unsigned b1 = __float_as_uint(sK[bn * 68 + bd + 4]);
        mma_tf32(sc[ni], a0, a1, a2, a3, b0, b1);
      }
    }
    const int rl = w * 16 + (lane >> 2);
#pragma unroll
    for (int ni = 0; ni < 8; ni++) {
      int c = ni * 8 + 2 * (lane & 3);
      float a0 = sMadd[c], a1 = sMadd[c + 1];
      float p0 = __expf(sc[ni][0] + a0 - mr0) * il0;
      float p1 = __expf(sc[ni][1] + a1 - mr0) * il0;
      float p2 = __expf(sc[ni][2] + a0 - mr1) * il1;
      float p3 = __expf(sc[ni][3] + a1 - mr1) * il1;
      sP[rl * 68 + c] = p0;       sP[rl * 68 + c + 1] = p1;
      sP[(rl + 8) * 68 + c] = p2; sP[(rl + 8) * 68 + c + 1] = p3;
    }
    __syncwarp();
    if (attn) {
      size_t abase = ((size_t)(b * H + h) * S + q0 + w * 16) * S + k0;
      for (int i = lane; i < 256; i += 32) {
        int r = i >> 4, c = (i & 15) * 4;
        float4 v = *(const float4*)&sP[(w * 16 + r) * 68 + c];
        *(float4*)&attn[abase + (size_t)r * S + c] = v;
      }
    }
#pragma unroll
    for (int ks = 0; ks < 8; ks++) {
      int ar = w * 16 + (lane >> 2), ac = ks * 8 + (lane & 3);
      unsigned a0 = f2tf(sP[ar * 68 + ac]);
      unsigned a1 = f2tf(sP[(ar + 8) * 68 + ac]);
      unsigned a2 = f2tf(sP[ar * 68 + ac + 4]);
      unsigned a3 = f2tf(sP[(ar + 8) * 68 + ac + 4]);
#pragma unroll
      for (int ni = 0; ni < 8; ni++) {
        unsigned b0 = __float_as_uint(sV[(ks * 8 + (lane & 3)) * 72 + ni * 8 + (lane >> 2)]);
        unsigned b1 = __float_as_uint(sV[(ks * 8 + (lane & 3) + 4) * 72 + ni * 8 + (lane >> 2)]);
        mma_tf32(ctx[ni], a0, a1, a2, a3, b0, b1);
      }
    }
  }
#pragma unroll
  for (int ni = 0; ni < 8; ni++) {
    int c = h * DH + ni * 8 + 2 * (lane & 3);
    size_t r0 = (size_t)(b * S) + q0 + w * 16 + (lane >> 2);
    *(float2*)&g_ctx[r0 * D + c] = make_float2(ctx[ni][0], ctx[ni][1]);
    *(float2*)&g_ctx[(r0 + 8) * D + c] = make_float2(ctx[ni][2], ctx[ni][3]);
  }
}

// ---------------- launch ----------------------------------------------------
extern "C" void kernel_launch(void* const* d_in, const int* in_sizes, int n_in,
                              void* d_out, int out_size) {
  using namespace cfg;
  (void)in_sizes; (void)n_in;
  const float* qs   = (const float*)d_in[0];
  const float* ksrc = (const float*)d_in[1];
  const float* vs   = (const float*)d_in[2];
  const void*  mask = d_in[3];
  const float* Wq = (const float*)d_in[4];
  const float* bq = (const float*)d_in[5];
  const float* Wk = (const float*)d_in[6];
  const float* bk = (const float*)d_in[7];
  const float* Wv = (const float*)d_in[8];
  const float* bv = (const float*)d_in[9];
  const float* Wo = (const float*)d_in[10];
  const float* bo = (const float*)d_in[11];

  void *pq, *pk, *pv, *pctx, *pxs, *pcs, *pwT;
  cudaGetSymbolAddress(&pq, g_q);
  cudaGetSymbolAddress(&pk, g_k);
  cudaGetSymbolAddress(&pv, g_v);
  cudaGetSymbolAddress(&pctx, g_ctx);
  cudaGetSymbolAddress(&pxs, g_xs4);
  cudaGetSymbolAddress(&pcs, g_cs4);
  cudaGetSymbolAddress(&pwT, g_wT4);

  const uint2* xs = (const uint2*)pxs;
  const uint2* cs = (const uint2*)pcs;
  const uint2* wT = (const uint2*)pwT;
  const size_t XSZ = (size_t)MR * KH;   // uint2 per input
  const size_t WSZ = (size_t)D * KH;

  const size_t OUT_E = (size_t)B * S * D;
  const size_t ATTN_E = (size_t)B * H * S * S;
  float* out_ptr = (float*)d_out;
  float* attn_ptr = nullptr;
  size_t osz = (size_t)out_size;
  if (osz >= OUT_E + ATTN_E) {
    attn_ptr = out_ptr + OUT_E;
  } else if (osz == ATTN_E) {
    attn_ptr = out_ptr;
    out_ptr = nullptr;
  }

  const int SMEMP = pj::SMEM_BYTES;
  const int SMEM1 = (128 * 68 + 64 * 68 + 64) * (int)sizeof(float);
  const int SMEM2 = (128 * 68 + 64 * 68 + 64 * 72 + 128 * 68 + 64) * (int)sizeof(float);
  cudaFuncSetAttribute(proj2_kernel, cudaFuncAttributeMaxDynamicSharedMemorySize, SMEMP);
  cudaFuncSetAttribute(attn_pass1, cudaFuncAttributeMaxDynamicSharedMemorySize, SMEM1);
  cudaFuncSetAttribute(attn_pass2, cudaFuncAttributeMaxDynamicSharedMemorySize, SMEM2);

  detect_mask_kernel<<<1, 32>>>((const unsigned*)mask);

  // operand prep
  Ptr3 xin; xin.x[0] = qs; xin.x[1] = ksrc; xin.x[2] = vs;
  split_x3_kernel<<<dim3(MR * D / 4 / 256, 1, 3), 256>>>(xin, (uint4*)pxs);
  Ptr4 win; win.w[0] = Wq; win.w[1] = Wk; win.w[2] = Wv; win.w[3] = Wo;
  split_wT4_kernel<<<dim3(D / 64, D / 64, 4), 256>>>(win, (uint2*)pwT);

  // fused q/k/v projections (mode 2 = tf32+0.125 scale for q, 1 = tf32 for k/v)
  ProjJobs jq;
  jq.j[0] = ProjJob{xs + 0 * XSZ, wT + 0 * WSZ, bq, (float*)pq, 2};
  jq.j[1] = ProjJob{xs + 1 * XSZ, wT + 1 * WSZ, bk, (float*)pk, 1};
  jq.j[2] = ProjJob{xs + 2 * XSZ, wT + 2 * WSZ, bv, (float*)pv, 1};
  proj2_kernel<<<dim3(D / pj::BN, MR / pj::BM, 3), 256, SMEMP>>>(jq);

  dim3 agrid(S / 128, H, B);
  attn_pass1<<<agrid, 256, SMEM1>>>(mask);
  attn_pass2<<<agrid, 256, SMEM2>>>(mask, attn_ptr);

  // ctx split + output projection
  Ptr3 cin; cin.x[0] = (const float*)pctx; cin.x[1] = (const float*)pctx; cin.x[2] = (const float*)pctx;
  split_x3_kernel<<<dim3(MR * D / 4 / 256, 1, 1), 256>>>(cin, (uint4*)pcs);
  ProjJobs jo;
  jo.j[0] = ProjJob{cs, wT + 3 * WSZ, bo, out_ptr ? out_ptr : (float*)pq, 0};
  jo.j[1] = jo.j[0]; jo.j[2] = jo.j[0];
  proj2_kernel<<<dim3(D / pj::BN, MR / pj::BM, 1), 256, SMEMP>>>(jo);
}